// round 1
// baseline (speedup 1.0000x reference)
#include <cuda_runtime.h>
#include <cuda_bf16.h>
#include <math.h>

// Problem constants (fixed shapes)
#define BB 2
#define TT 4
#define NN 8192
#define CC 128
#define MM 1024
#define KK 9
#define HH 8
#define DHH 64
#define KDIM 130          // C + 2
#define QKVC 1536         // 3 * HH * DHH
#define OUT_ELEMS (BB*TT*MM*CC)   // 1048576
#define TAIL (BB*MM*2)            // 4096
#define QSTRIDE 1537      // padded row stride for s_qkv (odd -> conflict-free)

// ----------------------------------------------------------------------------
// Scratch (device globals; allocation-free)
// ----------------------------------------------------------------------------
__device__ int   g_pivot_idx[BB*MM];
__device__ int   g_nbr[BB*MM*KK];
__device__ float g_rel[BB*MM*KK*2];

// ----------------------------------------------------------------------------
// Kernel 1: farthest point sampling (one block per batch, 1024 threads)
// ----------------------------------------------------------------------------
__global__ void __launch_bounds__(1024) fps_kernel(const float* __restrict__ pos)
{
    const int bb  = blockIdx.x;
    const int tid = threadIdx.x;
    const float2* pb = (const float2*)(pos + (size_t)bb * NN * 2);

    float px[8], py[8], dist[8];
#pragma unroll
    for (int j = 0; j < 8; j++) {
        float2 v = pb[j * 1024 + tid];
        px[j] = v.x; py[j] = v.y; dist[j] = INFINITY;
    }

    __shared__ float s_val[32], s_x[32], s_y[32];
    __shared__ int   s_idx[32];
    __shared__ float s_bx, s_by;

    if (tid == 0) {
        float2 p0 = pb[0];
        s_bx = p0.x; s_by = p0.y;
        g_pivot_idx[bb * MM + 0] = 0;
    }
    __syncthreads();

    const unsigned full = 0xffffffffu;
    const int wid = tid >> 5, lane = tid & 31;

    for (int s = 1; s < MM; s++) {
        const float bx = s_bx, by = s_by;
        float bestv = -INFINITY; int besti = 0x7fffffff;
        float bpx = 0.f, bpy = 0.f;
#pragma unroll
        for (int j = 0; j < 8; j++) {
            float dx = __fsub_rn(px[j], bx);
            float dy = __fsub_rn(py[j], by);
            float d  = __fadd_rn(__fmul_rn(dx, dx), __fmul_rn(dy, dy));
            dist[j]  = fminf(dist[j], d);
            int gi = j * 1024 + tid;
            if (dist[j] > bestv || (dist[j] == bestv && gi < besti)) {
                bestv = dist[j]; besti = gi; bpx = px[j]; bpy = py[j];
            }
        }
#pragma unroll
        for (int off = 16; off > 0; off >>= 1) {
            float ov = __shfl_down_sync(full, bestv, off);
            int   oi = __shfl_down_sync(full, besti, off);
            float ox = __shfl_down_sync(full, bpx, off);
            float oy = __shfl_down_sync(full, bpy, off);
            if (ov > bestv || (ov == bestv && oi < besti)) {
                bestv = ov; besti = oi; bpx = ox; bpy = oy;
            }
        }
        if (lane == 0) { s_val[wid] = bestv; s_idx[wid] = besti; s_x[wid] = bpx; s_y[wid] = bpy; }
        __syncthreads();
        if (wid == 0) {
            bestv = s_val[lane]; besti = s_idx[lane]; bpx = s_x[lane]; bpy = s_y[lane];
#pragma unroll
            for (int off = 16; off > 0; off >>= 1) {
                float ov = __shfl_down_sync(full, bestv, off);
                int   oi = __shfl_down_sync(full, besti, off);
                float ox = __shfl_down_sync(full, bpx, off);
                float oy = __shfl_down_sync(full, bpy, off);
                if (ov > bestv || (ov == bestv && oi < besti)) {
                    bestv = ov; besti = oi; bpx = ox; bpy = oy;
                }
            }
            if (lane == 0) {
                s_bx = bpx; s_by = bpy;
                g_pivot_idx[bb * MM + s] = besti;
            }
        }
        __syncthreads();
    }
}

// ----------------------------------------------------------------------------
// Kernel 2: KNN (warp per pivot) + writes pivot_pos to output tail
// ----------------------------------------------------------------------------
__global__ void __launch_bounds__(256) knn_kernel(const float* __restrict__ pos,
                                                  float* __restrict__ outp,
                                                  int write_tail)
{
    const int gw   = blockIdx.x * (blockDim.x >> 5) + (threadIdx.x >> 5);
    const int lane = threadIdx.x & 31;
    const int bb   = gw >> 10;
    const float2* pb = (const float2*)(pos + (size_t)bb * NN * 2);
    const unsigned full = 0xffffffffu;

    const int pidx = g_pivot_idx[gw];
    const float2 pv = pb[pidx];
    const float a = __fadd_rn(__fmul_rn(pv.x, pv.x), __fmul_rn(pv.y, pv.y));

    float d[9]; int id[9];
#pragma unroll
    for (int q = 0; q < 9; q++) { d[q] = INFINITY; id[q] = 0x7fffffff; }

    for (int p = lane; p < NN; p += 32) {
        float2 q2 = pb[p];
        float b2  = __fadd_rn(__fmul_rn(q2.x, q2.x), __fmul_rn(q2.y, q2.y));
        float dot = __fadd_rn(__fmul_rn(pv.x, q2.x), __fmul_rn(pv.y, q2.y));
        float d2  = __fsub_rn(__fadd_rn(a, b2), __fmul_rn(2.0f, dot));
        if (d2 < d[8] || (d2 == d[8] && p < id[8])) {
            d[8] = d2; id[8] = p;
#pragma unroll
            for (int q = 8; q > 0; q--) {
                bool sw = (d[q] < d[q-1]) || (d[q] == d[q-1] && id[q] < id[q-1]);
                if (sw) {
                    float tv = d[q]; d[q] = d[q-1]; d[q-1] = tv;
                    int   ti = id[q]; id[q] = id[q-1]; id[q-1] = ti;
                }
            }
        }
    }

    // merge 32 sorted lists, pop 9 global minima (lexicographic (d2, idx))
#pragma unroll
    for (int r = 0; r < 9; r++) {
        float bv = d[0]; int bi = id[0]; int bl = lane;
#pragma unroll
        for (int off = 16; off > 0; off >>= 1) {
            float ov = __shfl_down_sync(full, bv, off);
            int   oi = __shfl_down_sync(full, bi, off);
            int   ol = __shfl_down_sync(full, bl, off);
            if (ov < bv || (ov == bv && oi < bi)) { bv = ov; bi = oi; bl = ol; }
        }
        bi = __shfl_sync(full, bi, 0);
        bl = __shfl_sync(full, bl, 0);
        if (lane == bl) {
#pragma unroll
            for (int q = 0; q < 8; q++) { d[q] = d[q+1]; id[q] = id[q+1]; }
            d[8] = INFINITY; id[8] = 0x7fffffff;
        }
        if (lane == 0) {
            g_nbr[gw * KK + r] = bi;
            float2 q2 = pb[bi];
            g_rel[(gw * KK + r) * 2 + 0] = __fsub_rn(q2.x, pv.x);
            g_rel[(gw * KK + r) * 2 + 1] = __fsub_rn(q2.y, pv.y);
        }
    }
    if (lane == 0 && write_tail) {
        outp[OUT_ELEMS + gw * 2 + 0] = pv.x;
        outp[OUT_ELEMS + gw * 2 + 1] = pv.y;
    }
}

// ----------------------------------------------------------------------------
// sin/cos with explicit Cody-Waite range reduction (safe under fast-math)
// ----------------------------------------------------------------------------
__device__ __forceinline__ void sincos_red(float f, float* sn, float* cs)
{
    const float INV2PI = 0.15915494309189535f;
    const float C1 = 6.28318548202514648f;     // 2*pi hi
    const float C2 = -1.74845560e-7f;          // 2*pi - hi
    float kq = rintf(f * INV2PI);
    float r = fmaf(-kq, C1, f);
    r = fmaf(-kq, C2, r);
    *sn = sinf(r);
    *cs = cosf(r);
}

// ----------------------------------------------------------------------------
// Kernel 3: fused gather + QKV GEMM + RoPE + attention + mean + out-proj
// One block per (b, t, m) group; 256 threads.
// ----------------------------------------------------------------------------
__global__ void __launch_bounds__(256) group_kernel(const float* __restrict__ x,
                                                    const float* __restrict__ Wq,
                                                    const float* __restrict__ Wo,
                                                    const float* __restrict__ bo,
                                                    float* __restrict__ out)
{
    extern __shared__ float sm[];
    float* s_qkv  = sm;                        // 9 * QSTRIDE
    float* s_xin  = s_qkv + 9 * QSTRIDE;       // 9 * 132
    float* s_dots = s_xin + 9 * 132;           // 648
    float* s_w    = s_dots + 648;              // 72
    float* s_ob   = s_w + 72;                  // 512
    float* s_red  = s_ob + 512;                // 256
    float* s_rel  = s_red + 256;               // 18
    int*   s_nbr  = (int*)(s_rel + 18);        // 9

    const int g   = blockIdx.x;
    const int bb  = g >> 12;
    const int tt  = (g >> 10) & 3;
    const int mi  = g & 1023;
    const int tid = threadIdx.x;
    const int base = (bb << 10) + mi;          // b*M + m

    if (tid < 9)  s_nbr[tid] = g_nbr[base * KK + tid];
    if (tid < 18) s_rel[tid] = g_rel[base * KK * 2 + tid];
    __syncthreads();

    // gather xin = [x_g (9x128) | rel (9x2)]
    const float* xb = x + ((size_t)(bb * TT + tt)) * NN * CC;
    for (int idx = tid; idx < 9 * 128; idx += 256) {
        int sl = idx >> 7, c = idx & 127;
        s_xin[sl * 132 + c] = xb[(size_t)s_nbr[sl] * CC + c];
    }
    if (tid < 18) {
        int sl = tid >> 1, c = tid & 1;
        s_xin[sl * 132 + 128 + c] = s_rel[tid];
    }
    __syncthreads();

    // QKV GEMM: (9 x 130) @ (130 x 1536), thread owns cols {tid + j*256}
    float acc[54];
#pragma unroll
    for (int i = 0; i < 54; i++) acc[i] = 0.f;

    const float* Wbase = Wq + tid;
    float wv[6];
#pragma unroll
    for (int j = 0; j < 6; j++) wv[j] = Wbase[0 * QKVC + j * 256];

    for (int k = 0; k < KDIM; k++) {
        float a9[9];
#pragma unroll
        for (int s = 0; s < 9; s++) a9[s] = s_xin[s * 132 + k];
        float nw[6];
        int kn = (k + 1 < KDIM) ? (k + 1) : k;
#pragma unroll
        for (int j = 0; j < 6; j++) nw[j] = Wbase[kn * QKVC + j * 256];
#pragma unroll
        for (int s = 0; s < 9; s++)
#pragma unroll
            for (int j = 0; j < 6; j++)
                acc[s * 6 + j] = fmaf(a9[s], wv[j], acc[s * 6 + j]);
#pragma unroll
        for (int j = 0; j < 6; j++) wv[j] = nw[j];
    }
#pragma unroll
    for (int s = 0; s < 9; s++)
#pragma unroll
        for (int j = 0; j < 6; j++)
            s_qkv[s * QSTRIDE + tid + j * 256] = acc[s * 6 + j];
    __syncthreads();

    // 2D RoPE on q,k. tid -> (head, half, i): 8*2*16 = 256
    {
        const int h = tid >> 5, half = (tid >> 4) & 1, i = tid & 15;
        const float invf = __powf(10000.0f, -(float)i * (1.0f / 16.0f));
        const int bq = h * 64 + half * 32 + i;
#pragma unroll
        for (int s = 0; s < 9; s++) {
            float coord = s_rel[s * 2 + half];
            float f = coord * 2048.0f * invf;
            float sn, cs;
            sincos_red(f, &sn, &cs);
            float* row = s_qkv + s * QSTRIDE;
            float qa = row[bq], qb = row[bq + 16];
            row[bq]      = qa * cs - qb * sn;
            row[bq + 16] = qb * cs + qa * sn;
            float ka = row[512 + bq], kb = row[512 + bq + 16];
            row[512 + bq]      = ka * cs - kb * sn;
            row[512 + bq + 16] = kb * cs + ka * sn;
        }
    }
    __syncthreads();

    // dots[h][i][j] = scale * q_i . k_j
    for (int idx = tid; idx < 648; idx += 256) {
        int h = idx / 81, r = idx - h * 81;
        int qi = r / 9, kj = r - qi * 9;
        const float* qp = s_qkv + qi * QSTRIDE + h * 64;
        const float* kp = s_qkv + kj * QSTRIDE + 512 + h * 64;
        float a2 = 0.f;
#pragma unroll
        for (int dd = 0; dd < 64; dd++) a2 = fmaf(qp[dd], kp[dd], a2);
        s_dots[idx] = a2 * 0.125f;
    }
    __syncthreads();

    // softmax per (h,i) row
    if (tid < 72) {
        float* row = s_dots + tid * 9;
        float mx = row[0];
#pragma unroll
        for (int j = 1; j < 9; j++) mx = fmaxf(mx, row[j]);
        float sum = 0.f;
#pragma unroll
        for (int j = 0; j < 9; j++) { float e = expf(row[j] - mx); row[j] = e; sum += e; }
        float inv = 1.0f / sum;
#pragma unroll
        for (int j = 0; j < 9; j++) row[j] *= inv;
    }
    __syncthreads();

    // column sums of attn: w[h][j] = sum_i attn[h][i][j]
    if (tid < 72) {
        int h = tid / 9, j = tid - h * 9;
        float s2 = 0.f;
#pragma unroll
        for (int i = 0; i < 9; i++) s2 += s_dots[(h * 9 + i) * 9 + j];
        s_w[tid] = s2;
    }
    __syncthreads();

    // obar[c] = (1/9) * sum_j w[h][j] * v[j][d]  (mean commutes with out-proj)
    for (int c = tid; c < 512; c += 256) {
        int h = c >> 6, dd = c & 63;
        float a3 = 0.f;
#pragma unroll
        for (int j = 0; j < 9; j++)
            a3 = fmaf(s_w[h * 9 + j], s_qkv[j * QSTRIDE + 1024 + h * 64 + dd], a3);
        s_ob[c] = a3 * (1.0f / 9.0f);
    }
    __syncthreads();

    // out-projection: obar(512) @ W_out(512x128) + b_out
    {
        int c = tid & 127, part = tid >> 7;
        float a4 = 0.f;
        const float* wp = Wo + c;
        int k0 = part * 256;
        for (int k = k0; k < k0 + 256; k++) a4 = fmaf(s_ob[k], wp[(size_t)k * 128], a4);
        s_red[tid] = a4;
        __syncthreads();
        if (tid < 128)
            out[(size_t)g * 128 + tid] = s_red[tid] + s_red[tid + 128] + bo[tid];
    }
}

// ----------------------------------------------------------------------------
// Launch
// ----------------------------------------------------------------------------
extern "C" void kernel_launch(void* const* d_in, const int* in_sizes, int n_in,
                              void* d_out, int out_size)
{
    const float* x   = (const float*)d_in[0];
    const float* pos = (const float*)d_in[1];
    const float* Wq  = (const float*)d_in[2];
    const float* Wo  = (const float*)d_in[3];
    const float* bo  = (const float*)d_in[4];
    float* out = (float*)d_out;

    int write_tail = (out_size >= OUT_ELEMS + TAIL) ? 1 : 0;

    const int smem_bytes = (9 * QSTRIDE + 9 * 132 + 648 + 72 + 512 + 256 + 18 + 16) * 4;
    cudaFuncSetAttribute(group_kernel, cudaFuncAttributeMaxDynamicSharedMemorySize, smem_bytes);

    fps_kernel<<<BB, 1024>>>(pos);
    knn_kernel<<<(BB * MM) / 8, 256>>>(pos, out, write_tail);
    group_kernel<<<BB * TT * MM, 256, smem_bytes>>>(x, Wq, Wo, bo, out);
}

// round 2
// speedup vs baseline: 1.1727x; 1.1727x over previous
#include <cuda_runtime.h>
#include <cuda_bf16.h>
#include <math.h>

// Problem constants (fixed shapes)
#define BB 2
#define TT 4
#define NN 8192
#define CC 128
#define MM 1024
#define KK 9
#define HH 8
#define DHH 64
#define KDIM 130          // C + 2
#define QKVC 1536         // 3 * HH * DHH
#define OUT_ELEMS (BB*TT*MM*CC)   // 1048576
#define TAIL (BB*MM*2)            // 4096
#define QSTRIDE 1540      // padded row stride for s_qkv (16B aligned rows)
#define NROPE (BB*MM*KK*32)       // 589824

// ----------------------------------------------------------------------------
// Scratch (device globals; allocation-free)
// ----------------------------------------------------------------------------
__device__ int   g_pivot_idx[BB*MM];
__device__ int   g_nbr[BB*MM*KK];
__device__ float g_rel[BB*MM*KK*2];
__device__ float g_rsin[NROPE];
__device__ float g_rcos[NROPE];

// ----------------------------------------------------------------------------
// Kernel 1: farthest point sampling (one block per batch, 1024 threads)
// Packed u64 key = (dist_bits << 32) | ~idx  -> max() == (max dist, min idx)
// ----------------------------------------------------------------------------
__global__ void __launch_bounds__(1024) fps_kernel(const float* __restrict__ pos)
{
    const int bb  = blockIdx.x;
    const int tid = threadIdx.x;
    const float2* pb = (const float2*)(pos + (size_t)bb * NN * 2);

    float px[8], py[8], dist[8];
#pragma unroll
    for (int j = 0; j < 8; j++) {
        float2 v = pb[j * 1024 + tid];
        px[j] = v.x; py[j] = v.y; dist[j] = INFINITY;
    }

    __shared__ unsigned long long s_key[32];
    __shared__ float s_bx, s_by;

    if (tid == 0) {
        float2 p0 = pb[0];
        s_bx = p0.x; s_by = p0.y;
        g_pivot_idx[bb * MM + 0] = 0;
    }
    __syncthreads();

    const unsigned full = 0xffffffffu;
    const int wid = tid >> 5, lane = tid & 31;

    for (int s = 1; s < MM; s++) {
        const float bx = s_bx, by = s_by;
        unsigned long long key = 0ULL;
#pragma unroll
        for (int j = 0; j < 8; j++) {
            // numerically identical to reference: (dx*dx) + (dy*dy), no FMA
            float dx = __fsub_rn(px[j], bx);
            float dy = __fsub_rn(py[j], by);
            float d  = __fadd_rn(__fmul_rn(dx, dx), __fmul_rn(dy, dy));
            dist[j]  = fminf(dist[j], d);
            int gi = j * 1024 + tid;
            unsigned long long k2 = ((unsigned long long)__float_as_uint(dist[j]) << 32)
                                  | (unsigned)(~gi);
            key = (k2 > key) ? k2 : key;
        }
#pragma unroll
        for (int off = 16; off > 0; off >>= 1) {
            unsigned long long ok = __shfl_down_sync(full, key, off);
            key = (ok > key) ? ok : key;
        }
        if (lane == 0) s_key[wid] = key;
        __syncthreads();
        if (wid == 0) {
            key = s_key[lane];
#pragma unroll
            for (int off = 16; off > 0; off >>= 1) {
                unsigned long long ok = __shfl_down_sync(full, key, off);
                key = (ok > key) ? ok : key;
            }
            if (lane == 0) {
                int besti = (int)(~(unsigned)(key & 0xffffffffu));
                float2 bp = pb[besti];
                s_bx = bp.x; s_by = bp.y;
                g_pivot_idx[bb * MM + s] = besti;
            }
        }
        __syncthreads();
    }
}

// ----------------------------------------------------------------------------
// Kernel 2: KNN (warp per pivot) + writes pivot_pos to output tail
// ----------------------------------------------------------------------------
__global__ void __launch_bounds__(256) knn_kernel(const float* __restrict__ pos,
                                                  float* __restrict__ outp,
                                                  int write_tail)
{
    const int gw   = blockIdx.x * (blockDim.x >> 5) + (threadIdx.x >> 5);
    const int lane = threadIdx.x & 31;
    const int bb   = gw >> 10;
    const float2* pb = (const float2*)(pos + (size_t)bb * NN * 2);
    const unsigned full = 0xffffffffu;

    const int pidx = g_pivot_idx[gw];
    const float2 pv = pb[pidx];
    const float a = __fadd_rn(__fmul_rn(pv.x, pv.x), __fmul_rn(pv.y, pv.y));

    float d[9]; int id[9];
#pragma unroll
    for (int q = 0; q < 9; q++) { d[q] = INFINITY; id[q] = 0x7fffffff; }

    for (int p = lane; p < NN; p += 32) {
        float2 q2 = pb[p];
        float b2  = __fadd_rn(__fmul_rn(q2.x, q2.x), __fmul_rn(q2.y, q2.y));
        float dot = __fadd_rn(__fmul_rn(pv.x, q2.x), __fmul_rn(pv.y, q2.y));
        float d2  = __fsub_rn(__fadd_rn(a, b2), __fmul_rn(2.0f, dot));
        if (d2 < d[8] || (d2 == d[8] && p < id[8])) {
            d[8] = d2; id[8] = p;
#pragma unroll
            for (int q = 8; q > 0; q--) {
                bool sw = (d[q] < d[q-1]) || (d[q] == d[q-1] && id[q] < id[q-1]);
                if (sw) {
                    float tv = d[q]; d[q] = d[q-1]; d[q-1] = tv;
                    int   ti = id[q]; id[q] = id[q-1]; id[q-1] = ti;
                }
            }
        }
    }

#pragma unroll
    for (int r = 0; r < 9; r++) {
        float bv = d[0]; int bi = id[0]; int bl = lane;
#pragma unroll
        for (int off = 16; off > 0; off >>= 1) {
            float ov = __shfl_down_sync(full, bv, off);
            int   oi = __shfl_down_sync(full, bi, off);
            int   ol = __shfl_down_sync(full, bl, off);
            if (ov < bv || (ov == bv && oi < bi)) { bv = ov; bi = oi; bl = ol; }
        }
        bi = __shfl_sync(full, bi, 0);
        bl = __shfl_sync(full, bl, 0);
        if (lane == bl) {
#pragma unroll
            for (int q = 0; q < 8; q++) { d[q] = d[q+1]; id[q] = id[q+1]; }
            d[8] = INFINITY; id[8] = 0x7fffffff;
        }
        if (lane == 0) {
            g_nbr[gw * KK + r] = bi;
            float2 q2 = pb[bi];
            g_rel[(gw * KK + r) * 2 + 0] = __fsub_rn(q2.x, pv.x);
            g_rel[(gw * KK + r) * 2 + 1] = __fsub_rn(q2.y, pv.y);
        }
    }
    if (lane == 0 && write_tail) {
        outp[OUT_ELEMS + gw * 2 + 0] = pv.x;
        outp[OUT_ELEMS + gw * 2 + 1] = pv.y;
    }
}

// ----------------------------------------------------------------------------
// sin/cos with explicit Cody-Waite range reduction (safe under fast-math)
// ----------------------------------------------------------------------------
__device__ __forceinline__ void sincos_red(float f, float* sn, float* cs)
{
    const float INV2PI = 0.15915494309189535f;
    const float C1 = 6.28318548202514648f;
    const float C2 = -1.74845560e-7f;
    float kq = rintf(f * INV2PI);
    float r = fmaf(-kq, C1, f);
    r = fmaf(-kq, C2, r);
    *sn = sinf(r);
    *cs = cosf(r);
}

// ----------------------------------------------------------------------------
// Kernel 2.5: precompute RoPE sin/cos per (b,m,slot,half,i) -- t-invariant
// ----------------------------------------------------------------------------
__global__ void __launch_bounds__(256) rope_kernel()
{
    int idx = blockIdx.x * 256 + threadIdx.x;
    if (idx >= NROPE) return;
    int i    = idx & 15;
    int half = (idx >> 4) & 1;
    int rest = idx >> 5;
    int s    = rest % 9;
    int g    = rest / 9;
    float rel = g_rel[(g * KK + s) * 2 + half];
    float invf = __powf(10000.0f, -(float)i * (1.0f / 16.0f));
    float f = rel * 2048.0f * invf;
    float sn, cs;
    sincos_red(f, &sn, &cs);
    g_rsin[idx] = sn;
    g_rcos[idx] = cs;
}

// ----------------------------------------------------------------------------
// Kernel 3: fused gather + QKV GEMM + RoPE + attention + mean + out-proj
// One block per (b, t, m) group; 256 threads.
// Column ownership: thread owns cols [4*tid,4*tid+4) and [1024+2*tid,+2)
// so weight loads per k are one LDG.128 + one LDG.64.
// ----------------------------------------------------------------------------
__global__ void __launch_bounds__(256) group_kernel(const float* __restrict__ x,
                                                    const float* __restrict__ Wq,
                                                    const float* __restrict__ Wo,
                                                    const float* __restrict__ bo,
                                                    float* __restrict__ out)
{
    extern __shared__ float sm[];
    float* s_qkv  = sm;                        // 9 * QSTRIDE
    float* s_xin  = s_qkv + 9 * QSTRIDE;       // 9 * 132
    float* s_dots = s_xin + 9 * 132;           // 648
    float* s_w    = s_dots + 648;              // 72
    float* s_ob   = s_w + 72;                  // 512
    float* s_red  = s_ob + 512;                // 256
    float* s_rel  = s_red + 256;               // 18
    int*   s_nbr  = (int*)(s_rel + 18);        // 9 (+pad)

    const int g   = blockIdx.x;
    const int bb  = g >> 12;
    const int tt  = (g >> 10) & 3;
    const int mi  = g & 1023;
    const int tid = threadIdx.x;
    const int base = (bb << 10) + mi;          // b*M + m

    if (tid < 9)  s_nbr[tid] = g_nbr[base * KK + tid];
    if (tid < 18) s_rel[tid] = g_rel[base * KK * 2 + tid];
    __syncthreads();

    // gather xin = [x_g (9x128) | rel (9x2)]  (float4 loads)
    const float* xb = x + ((size_t)(bb * TT + tt)) * NN * CC;
    for (int idx = tid; idx < 9 * 32; idx += 256) {
        int sl = idx >> 5, c4 = idx & 31;
        float4 v = *(const float4*)(xb + (size_t)s_nbr[sl] * CC + c4 * 4);
        *(float4*)(s_xin + sl * 132 + c4 * 4) = v;
    }
    if (tid < 18) {
        int sl = tid >> 1, c = tid & 1;
        s_xin[sl * 132 + 128 + c] = s_rel[tid];
    }
    __syncthreads();

    // QKV GEMM: (9 x 130) @ (130 x 1536)
    float acc[54];
#pragma unroll
    for (int i = 0; i < 54; i++) acc[i] = 0.f;

    const float* W4 = Wq + 4 * tid;
    const float* W2 = Wq + 1024 + 2 * tid;

    float4 w4 = *(const float4*)(W4);
    float2 w2 = *(const float2*)(W2);

#pragma unroll 2
    for (int k = 0; k < KDIM; k++) {
        int kn = (k + 1 < KDIM) ? (k + 1) : k;
        float4 n4 = *(const float4*)(W4 + (size_t)kn * QKVC);
        float2 n2 = *(const float2*)(W2 + (size_t)kn * QKVC);
        float a9[9];
#pragma unroll
        for (int s = 0; s < 9; s++) a9[s] = s_xin[s * 132 + k];
#pragma unroll
        for (int s = 0; s < 9; s++) {
            acc[s*6+0] = fmaf(a9[s], w4.x, acc[s*6+0]);
            acc[s*6+1] = fmaf(a9[s], w4.y, acc[s*6+1]);
            acc[s*6+2] = fmaf(a9[s], w4.z, acc[s*6+2]);
            acc[s*6+3] = fmaf(a9[s], w4.w, acc[s*6+3]);
            acc[s*6+4] = fmaf(a9[s], w2.x, acc[s*6+4]);
            acc[s*6+5] = fmaf(a9[s], w2.y, acc[s*6+5]);
        }
        w4 = n4; w2 = n2;
    }
#pragma unroll
    for (int s = 0; s < 9; s++) {
        *(float4*)(s_qkv + s * QSTRIDE + 4 * tid) =
            make_float4(acc[s*6+0], acc[s*6+1], acc[s*6+2], acc[s*6+3]);
        *(float2*)(s_qkv + s * QSTRIDE + 1024 + 2 * tid) =
            make_float2(acc[s*6+4], acc[s*6+5]);
    }
    __syncthreads();

    // 2D RoPE on q,k using precomputed sin/cos. tid -> (head, half, i)
    {
        const int h = tid >> 5, half = (tid >> 4) & 1, i = tid & 15;
        const int bq = h * 64 + half * 32 + i;
#pragma unroll
        for (int s = 0; s < 9; s++) {
            int ridx = ((base * KK + s) * 2 + half) * 16 + i;
            float sn = g_rsin[ridx];
            float cs = g_rcos[ridx];
            float* row = s_qkv + s * QSTRIDE;
            float qa = row[bq], qb = row[bq + 16];
            row[bq]      = qa * cs - qb * sn;
            row[bq + 16] = qb * cs + qa * sn;
            float ka = row[512 + bq], kb = row[512 + bq + 16];
            row[512 + bq]      = ka * cs - kb * sn;
            row[512 + bq + 16] = kb * cs + ka * sn;
        }
    }
    __syncthreads();

    // dots[h][i][j] = scale * q_i . k_j
    for (int idx = tid; idx < 648; idx += 256) {
        int h = idx / 81, r = idx - h * 81;
        int qi = r / 9, kj = r - qi * 9;
        const float* qp = s_qkv + qi * QSTRIDE + h * 64;
        const float* kp = s_qkv + kj * QSTRIDE + 512 + h * 64;
        float a2 = 0.f;
#pragma unroll
        for (int dd = 0; dd < 64; dd++) a2 = fmaf(qp[dd], kp[dd], a2);
        s_dots[idx] = a2 * 0.125f;
    }
    __syncthreads();

    // softmax per (h,i) row
    if (tid < 72) {
        float* row = s_dots + tid * 9;
        float mx = row[0];
#pragma unroll
        for (int j = 1; j < 9; j++) mx = fmaxf(mx, row[j]);
        float sum = 0.f;
#pragma unroll
        for (int j = 0; j < 9; j++) { float e = expf(row[j] - mx); row[j] = e; sum += e; }
        float inv = 1.0f / sum;
#pragma unroll
        for (int j = 0; j < 9; j++) row[j] *= inv;
    }
    __syncthreads();

    // column sums of attn: w[h][j] = sum_i attn[h][i][j]
    if (tid < 72) {
        int h = tid / 9, j = tid - h * 9;
        float s2 = 0.f;
#pragma unroll
        for (int i = 0; i < 9; i++) s2 += s_dots[(h * 9 + i) * 9 + j];
        s_w[tid] = s2;
    }
    __syncthreads();

    // obar[c] = (1/9) * sum_j w[h][j] * v[j][d]  (mean commutes with out-proj)
    for (int c = tid; c < 512; c += 256) {
        int h = c >> 6, dd = c & 63;
        float a3 = 0.f;
#pragma unroll
        for (int j = 0; j < 9; j++)
            a3 = fmaf(s_w[h * 9 + j], s_qkv[j * QSTRIDE + 1024 + h * 64 + dd], a3);
        s_ob[c] = a3 * (1.0f / 9.0f);
    }
    __syncthreads();

    // out-projection: obar(512) @ W_out(512x128) + b_out
    {
        int c = tid & 127, part = tid >> 7;
        float a4 = 0.f;
        const float* wp = Wo + c;
        int k0 = part * 256;
        for (int k = k0; k < k0 + 256; k++) a4 = fmaf(s_ob[k], wp[(size_t)k * 128], a4);
        s_red[tid] = a4;
        __syncthreads();
        if (tid < 128)
            out[(size_t)g * 128 + tid] = s_red[tid] + s_red[tid + 128] + bo[tid];
    }
}

// ----------------------------------------------------------------------------
// Launch
// ----------------------------------------------------------------------------
extern "C" void kernel_launch(void* const* d_in, const int* in_sizes, int n_in,
                              void* d_out, int out_size)
{
    const float* x   = (const float*)d_in[0];
    const float* pos = (const float*)d_in[1];
    const float* Wq  = (const float*)d_in[2];
    const float* Wo  = (const float*)d_in[3];
    const float* bo  = (const float*)d_in[4];
    float* out = (float*)d_out;

    int write_tail = (out_size >= OUT_ELEMS + TAIL) ? 1 : 0;

    const int smem_bytes = (9 * QSTRIDE + 9 * 132 + 648 + 72 + 512 + 256 + 18 + 16) * 4;
    static int smem_set = 0;
    if (!smem_set) {
        cudaFuncSetAttribute(group_kernel, cudaFuncAttributeMaxDynamicSharedMemorySize, smem_bytes);
        smem_set = 1;
    }

    fps_kernel<<<BB, 1024>>>(pos);
    knn_kernel<<<(BB * MM) / 8, 256>>>(pos, out, write_tail);
    rope_kernel<<<(NROPE + 255) / 256, 256>>>();
    group_kernel<<<BB * TT * MM, 256, smem_bytes>>>(x, Wq, Wo, bo, out);
}

// round 5
// speedup vs baseline: 1.5841x; 1.3509x over previous
#include <cuda_runtime.h>
#include <cuda_bf16.h>
#include <math.h>
#include <stdint.h>

// Problem constants (fixed shapes)
#define BB 2
#define TT 4
#define NN 8192
#define CC 128
#define MM 1024
#define KK 9
#define HH 8
#define DHH 64
#define QKVC 1536         // 3 * HH * DHH
#define OUT_ELEMS (BB*TT*MM*CC)   // 1048576
#define TAIL (BB*MM*2)            // 4096
#define QSTRIDE 1540
#define NROPE (BB*MM*KK*32)       // 589824
#define NROWS (BB*TT*NN)          // 65536 rows of P
#define NTILES 12                 // 1536/128
#define MTILES 512                // 65536/128

// smem row stride for mma tiles: 136 bf16 = 272 bytes (conflict-free ldmatrix)
#define TSTRIDE 136
#define TILE_B  (128 * TSTRIDE * 2)   // 34816 bytes per 128x128 bf16 tile

// ----------------------------------------------------------------------------
// Scratch (device globals; allocation-free)
// ----------------------------------------------------------------------------
__device__ int   g_pivot_idx[BB*MM];
__device__ int   g_nbr[BB*MM*KK];
__device__ float g_rel[BB*MM*KK*2];
__device__ float g_rsin[NROPE];
__device__ float g_rcos[NROPE];
__device__ float g_P[(size_t)NROWS * QKVC];                 // 402 MB scratch
__device__ float g_obar[BB*TT*MM * 512];                    // 16 MB
__device__ __align__(16) __nv_bfloat16 g_whi[NTILES*128*128];  // W1 bf16 hi, [ntile][n][k]
__device__ __align__(16) __nv_bfloat16 g_wlo[NTILES*128*128];  // W1 bf16 lo

// ----------------------------------------------------------------------------
// mma.sync / ldmatrix helpers (valid on plain sm_100)
// ----------------------------------------------------------------------------
__device__ __forceinline__ uint32_t smem_u32(const void* p) {
    uint32_t a;
    asm("{ .reg .u64 t; cvta.to.shared.u64 t, %1; cvt.u32.u64 %0, t; }" : "=r"(a) : "l"(p));
    return a;
}
__device__ __forceinline__ void ldsm_x4(uint32_t* r, uint32_t addr) {
    asm volatile("ldmatrix.sync.aligned.m8n8.x4.shared.b16 {%0,%1,%2,%3}, [%4];"
                 : "=r"(r[0]), "=r"(r[1]), "=r"(r[2]), "=r"(r[3]) : "r"(addr));
}
__device__ __forceinline__ void mma16816(float* c, const uint32_t* a, const uint32_t* b) {
    asm volatile("mma.sync.aligned.m16n8k16.row.col.f32.bf16.bf16.f32 "
                 "{%0,%1,%2,%3}, {%4,%5,%6,%7}, {%8,%9}, {%0,%1,%2,%3};"
                 : "+f"(c[0]), "+f"(c[1]), "+f"(c[2]), "+f"(c[3])
                 : "r"(a[0]), "r"(a[1]), "r"(a[2]), "r"(a[3]), "r"(b[0]), "r"(b[1]));
}

// ----------------------------------------------------------------------------
// Kernel 1: farthest point sampling (one block per batch, 512 threads)
// ----------------------------------------------------------------------------
__global__ void __launch_bounds__(512) fps_kernel(const float* __restrict__ pos)
{
    const int bb  = blockIdx.x;
    const int tid = threadIdx.x;
    const float2* pb = (const float2*)(pos + (size_t)bb * NN * 2);

    float px[16], py[16], dist[16];
#pragma unroll
    for (int j = 0; j < 16; j++) {
        float2 v = pb[j * 512 + tid];
        px[j] = v.x; py[j] = v.y; dist[j] = INFINITY;
    }

    __shared__ unsigned long long s_key[2][16];
    const int wid = tid >> 5, lane = tid & 31;

    float bx, by;
    { float2 p0 = pb[0]; bx = p0.x; by = p0.y; }
    if (tid == 0) g_pivot_idx[bb * MM] = 0;

    for (int s = 1; s < MM; s++) {
        unsigned bestd; int besti;
        {
            // numerically identical to reference: (dx*dx) + (dy*dy), no FMA
            float dx = __fsub_rn(px[0], bx), dy = __fsub_rn(py[0], by);
            float d  = __fadd_rn(__fmul_rn(dx, dx), __fmul_rn(dy, dy));
            dist[0]  = fminf(dist[0], d);
            bestd = __float_as_uint(dist[0]); besti = tid;
        }
#pragma unroll
        for (int j = 1; j < 16; j++) {
            float dx = __fsub_rn(px[j], bx), dy = __fsub_rn(py[j], by);
            float d  = __fadd_rn(__fmul_rn(dx, dx), __fmul_rn(dy, dy));
            dist[j]  = fminf(dist[j], d);
            unsigned db = __float_as_uint(dist[j]);
            if (db > bestd) { bestd = db; besti = j * 512 + tid; }
        }
        unsigned wmax = __reduce_max_sync(0xffffffffu, bestd);
        unsigned cand = (bestd == wmax) ? (unsigned)besti : 0x7fffffffu;
        unsigned wmin = __reduce_min_sync(0xffffffffu, cand);
        if (lane == 0)
            s_key[s & 1][wid] = ((unsigned long long)wmax << 32) | (unsigned)(~wmin);
        __syncthreads();
        unsigned long long best = s_key[s & 1][0];
#pragma unroll
        for (int w = 1; w < 16; w++) {
            unsigned long long k2 = s_key[s & 1][w];
            if (k2 > best) best = k2;
        }
        int bi = (int)(~(unsigned)(best & 0xffffffffu));
        float2 bp = pb[bi];
        bx = bp.x; by = bp.y;
        if (tid == 0) g_pivot_idx[bb * MM + s] = bi;
    }
}

// ----------------------------------------------------------------------------
// Kernel 2: KNN (warp per pivot) + writes pivot_pos to output tail
// ----------------------------------------------------------------------------
__global__ void __launch_bounds__(256) knn_kernel(const float* __restrict__ pos,
                                                  float* __restrict__ outp,
                                                  int write_tail)
{
    const int gw   = blockIdx.x * (blockDim.x >> 5) + (threadIdx.x >> 5);
    const int lane = threadIdx.x & 31;
    const int bb   = gw >> 10;
    const float2* pb = (const float2*)(pos + (size_t)bb * NN * 2);
    const unsigned full = 0xffffffffu;

    const int pidx = g_pivot_idx[gw];
    const float2 pv = pb[pidx];
    const float a = __fadd_rn(__fmul_rn(pv.x, pv.x), __fmul_rn(pv.y, pv.y));

    float d[9]; int id[9];
#pragma unroll
    for (int q = 0; q < 9; q++) { d[q] = INFINITY; id[q] = 0x7fffffff; }

    for (int p = lane; p < NN; p += 32) {
        float2 q2 = pb[p];
        float b2  = __fadd_rn(__fmul_rn(q2.x, q2.x), __fmul_rn(q2.y, q2.y));
        float dot = __fadd_rn(__fmul_rn(pv.x, q2.x), __fmul_rn(pv.y, q2.y));
        float d2  = __fsub_rn(__fadd_rn(a, b2), __fmul_rn(2.0f, dot));
        if (d2 < d[8] || (d2 == d[8] && p < id[8])) {
            d[8] = d2; id[8] = p;
#pragma unroll
            for (int q = 8; q > 0; q--) {
                bool sw = (d[q] < d[q-1]) || (d[q] == d[q-1] && id[q] < id[q-1]);
                if (sw) {
                    float tv = d[q]; d[q] = d[q-1]; d[q-1] = tv;
                    int   ti = id[q]; id[q] = id[q-1]; id[q-1] = ti;
                }
            }
        }
    }
#pragma unroll
    for (int r = 0; r < 9; r++) {
        float bv = d[0]; int bi = id[0]; int bl = lane;
#pragma unroll
        for (int off = 16; off > 0; off >>= 1) {
            float ov = __shfl_down_sync(full, bv, off);
            int   oi = __shfl_down_sync(full, bi, off);
            int   ol = __shfl_down_sync(full, bl, off);
            if (ov < bv || (ov == bv && oi < bi)) { bv = ov; bi = oi; bl = ol; }
        }
        bi = __shfl_sync(full, bi, 0);
        bl = __shfl_sync(full, bl, 0);
        if (lane == bl) {
#pragma unroll
            for (int q = 0; q < 8; q++) { d[q] = d[q+1]; id[q] = id[q+1]; }
            d[8] = INFINITY; id[8] = 0x7fffffff;
        }
        if (lane == 0) {
            g_nbr[gw * KK + r] = bi;
            float2 q2 = pb[bi];
            g_rel[(gw * KK + r) * 2 + 0] = __fsub_rn(q2.x, pv.x);
            g_rel[(gw * KK + r) * 2 + 1] = __fsub_rn(q2.y, pv.y);
        }
    }
    if (lane == 0 && write_tail) {
        outp[OUT_ELEMS + gw * 2 + 0] = pv.x;
        outp[OUT_ELEMS + gw * 2 + 1] = pv.y;
    }
}

// ----------------------------------------------------------------------------
// sin/cos with explicit Cody-Waite range reduction (safe under fast-math)
// ----------------------------------------------------------------------------
__device__ __forceinline__ void sincos_red(float f, float* sn, float* cs)
{
    const float INV2PI = 0.15915494309189535f;
    const float C1 = 6.28318548202514648f;
    const float C2 = -1.74845560e-7f;
    float kq = rintf(f * INV2PI);
    float r = fmaf(-kq, C1, f);
    r = fmaf(-kq, C2, r);
    *sn = sinf(r);
    *cs = cosf(r);
}

// Kernel 2.5: precompute RoPE sin/cos (t-invariant)
__global__ void __launch_bounds__(256) rope_kernel()
{
    int idx = blockIdx.x * 256 + threadIdx.x;
    if (idx >= NROPE) return;
    int i    = idx & 15;
    int half = (idx >> 4) & 1;
    int rest = idx >> 5;
    int s    = rest % 9;
    int g    = rest / 9;
    float rel = g_rel[(g * KK + s) * 2 + half];
    float invf = __powf(10000.0f, -(float)i * (1.0f / 16.0f));
    float f = rel * 2048.0f * invf;
    float sn, cs;
    sincos_red(f, &sn, &cs);
    g_rsin[idx] = sn;
    g_rcos[idx] = cs;
}

// ----------------------------------------------------------------------------
// Kernel 0: convert W1 (=W_qkv rows 0..127) into bf16 hi/lo, layout [ntile][n][k]
// ----------------------------------------------------------------------------
__global__ void __launch_bounds__(256) wprep_kernel(const float* __restrict__ Wq)
{
    int idx = blockIdx.x * 256 + threadIdx.x;
    if (idx >= NTILES * 16384) return;
    int ntile = idx >> 14;
    int e = idx & 16383;
    int n = e >> 7, k = e & 127;
    float w = Wq[(size_t)k * QKVC + ntile * 128 + n];
    __nv_bfloat16 hi = __float2bfloat16(w);
    __nv_bfloat16 lo = __float2bfloat16(w - __bfloat162float(hi));
    g_whi[idx] = hi;
    g_wlo[idx] = lo;
}

// ----------------------------------------------------------------------------
// Kernel 3: P = x @ W1 via mma.sync bf16 hi/lo (3 accumulation passes)
// one CTA per mtile (128 rows); loops over 12 ntiles.
// 8 warps: warp_m = wid&3 (32-row slice), warp_n = wid>>2 (64-col slice)
// ----------------------------------------------------------------------------
#define SM_AHI 0
#define SM_ALO (TILE_B)
#define SM_BHI (2*TILE_B)
#define SM_BLO (3*TILE_B)
#define GEMM_SMEM (4*TILE_B)

__global__ void __launch_bounds__(256, 1) gemm_kernel(const float* __restrict__ x)
{
    extern __shared__ char smem[];
    const uint32_t sb = smem_u32(smem);
    const int tid  = threadIdx.x;
    const int wid  = tid >> 5, lane = tid & 31;
    const int wm   = wid & 3;        // m-slice (32 rows)
    const int wn   = wid >> 2;       // n-slice (64 cols)
    const int mtile = blockIdx.x;

    // ---- load + convert A tile (128x128 fp32 -> bf16 hi/lo) ----
    {
        const float4* xa = (const float4*)(x + (size_t)mtile * 128 * 128);
        for (int i = tid; i < 4096; i += 256) {
            int row = i >> 5, c = (i & 31) * 4;
            float4 v = xa[i];
            __nv_bfloat16 h0 = __float2bfloat16(v.x);
            __nv_bfloat16 h1 = __float2bfloat16(v.y);
            __nv_bfloat16 h2 = __float2bfloat16(v.z);
            __nv_bfloat16 h3 = __float2bfloat16(v.w);
            __nv_bfloat16 l0 = __float2bfloat16(v.x - __bfloat162float(h0));
            __nv_bfloat16 l1 = __float2bfloat16(v.y - __bfloat162float(h1));
            __nv_bfloat16 l2 = __float2bfloat16(v.z - __bfloat162float(h2));
            __nv_bfloat16 l3 = __float2bfloat16(v.w - __bfloat162float(h3));
            __nv_bfloat162* dh = (__nv_bfloat162*)(smem + SM_AHI + (row * TSTRIDE + c) * 2);
            __nv_bfloat162* dl = (__nv_bfloat162*)(smem + SM_ALO + (row * TSTRIDE + c) * 2);
            __nv_bfloat162 hp0; hp0.x = h0; hp0.y = h1;
            __nv_bfloat162 hp1; hp1.x = h2; hp1.y = h3;
            __nv_bfloat162 lp0; lp0.x = l0; lp0.y = l1;
            __nv_bfloat162 lp1; lp1.x = l2; lp1.y = l3;
            dh[0] = hp0; dh[1] = hp1;
            dl[0] = lp0; dl[1] = lp1;
        }
    }

    // ldmatrix per-lane base offsets
    // A (x4): rows m0 + (lane&15), col half (lane>>4)*8
    const uint32_t a_off = (uint32_t)(((wm * 32 + (lane & 15)) * TSTRIDE + ((lane >> 4) << 3)) * 2);
    // B (x4, covers 2 n-frags): n row = n0 + ((lane>>4)<<3) + (lane&7), k half ((lane>>3)&1)*8
    const uint32_t b_off = (uint32_t)(((wn * 64 + ((lane >> 4) << 3) + (lane & 7)) * TSTRIDE
                                      + (((lane >> 3) & 1) << 3)) * 2);

    for (int nt = 0; nt < NTILES; nt++) {
        // copy B tiles (hi/lo) into padded smem
        __syncthreads();   // prior iteration's ldmatrix reads done
        {
            const uint4* bh = (const uint4*)(g_whi + (size_t)nt * 16384);
            const uint4* bl = (const uint4*)(g_wlo + (size_t)nt * 16384);
            for (int i = tid; i < 2048; i += 256) {
                int row = i >> 4, ch = i & 15;
                *(uint4*)(smem + SM_BHI + (row * TSTRIDE + ch * 8) * 2) = bh[i];
                *(uint4*)(smem + SM_BLO + (row * TSTRIDE + ch * 8) * 2) = bl[i];
            }
        }
        __syncthreads();

        float acc[64];
#pragma unroll
        for (int i = 0; i < 64; i++) acc[i] = 0.f;

        // 3 passes: (Ahi,Bhi), (Ahi,Blo), (Alo,Bhi)
#pragma unroll
        for (int pass = 0; pass < 3; pass++) {
            const uint32_t sa = sb + (pass == 2 ? SM_ALO : SM_AHI) + a_off;
            const uint32_t sbb = sb + (pass == 1 ? SM_BLO : SM_BHI) + b_off;
#pragma unroll
            for (int ks = 0; ks < 8; ks++) {
                uint32_t a0[4], a1[4];
                ldsm_x4(a0, sa + ks * 32);
                ldsm_x4(a1, sa + 16 * TSTRIDE * 2 + ks * 32);
#pragma unroll
                for (int j2 = 0; j2 < 4; j2++) {
                    uint32_t b[4];
                    ldsm_x4(b, sbb + j2 * 16 * TSTRIDE * 2 + ks * 32);
                    mma16816(acc + (0 * 8 + j2 * 2 + 0) * 4, a0, b);
                    mma16816(acc + (0 * 8 + j2 * 2 + 1) * 4, a0, b + 2);
                    mma16816(acc + (1 * 8 + j2 * 2 + 0) * 4, a1, b);
                    mma16816(acc + (1 * 8 + j2 * 2 + 1) * 4, a1, b + 2);
                }
            }
        }

        // epilogue: write fragment to g_P
        {
            const int rbase = mtile * 128 + wm * 32 + (lane >> 2);
            const int cbase = nt * 128 + wn * 64 + (lane & 3) * 2;
#pragma unroll
            for (int i = 0; i < 2; i++) {
#pragma unroll
                for (int j = 0; j < 8; j++) {
                    const float* c = acc + (i * 8 + j) * 4;
                    int r0 = rbase + i * 16;
                    int cc = cbase + j * 8;
                    *(float2*)(g_P + (size_t)r0 * QKVC + cc)       = make_float2(c[0], c[1]);
                    *(float2*)(g_P + (size_t)(r0 + 8) * QKVC + cc) = make_float2(c[2], c[3]);
                }
            }
        }
    }
}

// ----------------------------------------------------------------------------
// Kernel 4: gather P + rel update + RoPE + attention + mean -> g_obar
// ----------------------------------------------------------------------------
__global__ void __launch_bounds__(256) group_kernel(const float* __restrict__ Wq)
{
    extern __shared__ float sm[];
    float* s_qkv  = sm;                        // 9 * QSTRIDE
    float* s_dots = s_qkv + 9 * QSTRIDE;       // 648
    float* s_w    = s_dots + 648;              // 72
    float* s_rel  = s_w + 72;                  // 18
    int*   s_nbr  = (int*)(s_rel + 18);        // 9 (+pad)

    const int g   = blockIdx.x;
    const int bb  = g >> 12;
    const int tt  = (g >> 10) & 3;
    const int mi  = g & 1023;
    const int tid = threadIdx.x;
    const int base = (bb << 10) + mi;          // b*M + m

    if (tid < 9)  s_nbr[tid] = g_nbr[base * KK + tid];
    if (tid < 18) s_rel[tid] = g_rel[base * KK * 2 + tid];
    __syncthreads();

    // qkv[s] = P[nbr[s]] + rel_x * W2a + rel_y * W2b
    const float* Pbt = g_P + (size_t)((bb * TT + tt)) * NN * QKVC;
    const float* W2a = Wq + (size_t)128 * QKVC;
    const float* W2b = Wq + (size_t)129 * QKVC;
    for (int idx = tid; idx < 9 * 384; idx += 256) {
        int sl = idx / 384;
        int c4 = idx - sl * 384;
        float4 p  = *(const float4*)(Pbt + (size_t)s_nbr[sl] * QKVC + c4 * 4);
        float4 wa = *(const float4*)(W2a + c4 * 4);
        float4 wb = *(const float4*)(W2b + c4 * 4);
        float rx = s_rel[sl * 2], ry = s_rel[sl * 2 + 1];
        float4 r;
        r.x = p.x + rx * wa.x + ry * wb.x;
        r.y = p.y + rx * wa.y + ry * wb.y;
        r.z = p.z + rx * wa.z + ry * wb.z;
        r.w = p.w + rx * wa.w + ry * wb.w;
        *(float4*)(s_qkv + sl * QSTRIDE + c4 * 4) = r;
    }
    __syncthreads();

    // 2D RoPE on q,k using precomputed sin/cos. tid -> (head, half, i)
    {
        const int h = tid >> 5, half = (tid >> 4) & 1, i = tid & 15;
        const int bq = h * 64 + half * 32 + i;
#pragma unroll
        for (int s = 0; s < 9; s++) {
            int ridx = ((base * KK + s) * 2 + half) * 16 + i;
            float sn = g_rsin[ridx];
            float cs = g_rcos[ridx];
            float* row = s_qkv + s * QSTRIDE;
            float qa = row[bq], qb = row[bq + 16];
            row[bq]      = qa * cs - qb * sn;
            row[bq + 16] = qb * cs + qa * sn;
            float ka = row[512 + bq], kb = row[512 + bq + 16];
            row[512 + bq]      = ka * cs - kb * sn;
            row[512 + bq + 16] = kb * cs + ka * sn;
        }
    }
    __syncthreads();

    // dots[h][i][j] = scale * q_i . k_j
    for (int idx = tid; idx < 648; idx += 256) {
        int h = idx / 81, r = idx - h * 81;
        int qi = r / 9, kj = r - qi * 9;
        const float* qp = s_qkv + qi * QSTRIDE + h * 64;
        const float* kp = s_qkv + kj * QSTRIDE + 512 + h * 64;
        float a2 = 0.f;
#pragma unroll
        for (int dd = 0; dd < 64; dd++) a2 = fmaf(qp[dd], kp[dd], a2);
        s_dots[idx] = a2 * 0.125f;
    }
    __syncthreads();

    // softmax per (h,i) row
    if (tid < 72) {
        float* row = s_dots + tid * 9;
        float mx = row[0];
#pragma unroll
        for (int j = 1; j < 9; j++) mx = fmaxf(mx, row[j]);
        float sum = 0.f;
#pragma unroll
        for (int j = 0; j < 9; j++) { float e = expf(row[j] - mx); row[j] = e; sum += e; }
        float inv = 1.0f / sum;
#pragma unroll
        for (int j = 0; j < 9; j++) row[j] *= inv;
    }
    __syncthreads();

    // column sums of attn: w[h][j] = sum_i attn[h][i][j]
    if (tid < 72) {
        int h = tid / 9, j = tid - h * 9;
        float s2 = 0.f;
#pragma unroll
        for (int i = 0; i < 9; i++) s2 += s_dots[(h * 9 + i) * 9 + j];
        s_w[tid] = s2;
    }
    __syncthreads();

    // obar[c] = (1/9) * sum_j w[h][j] * v[j][d] -> global
    for (int c = tid; c < 512; c += 256) {
        int h = c >> 6, dd = c & 63;
        float a3 = 0.f;
#pragma unroll
        for (int j = 0; j < 9; j++)
            a3 = fmaf(s_w[h * 9 + j], s_qkv[j * QSTRIDE + 1024 + h * 64 + dd], a3);
        g_obar[(size_t)g * 512 + c] = a3 * (1.0f / 9.0f);
    }
}

// ----------------------------------------------------------------------------
// Kernel 5: out = obar @ W_out + b_out   (8192 x 128 x 512)
// ----------------------------------------------------------------------------
#define OPROWS 64
__global__ void __launch_bounds__(256) outproj_kernel(const float* __restrict__ Wo,
                                                      const float* __restrict__ bo,
                                                      float* __restrict__ out)
{
    extern __shared__ float smo[];
    float* sA = smo;             // 64 x 128
    float* sB = sA + OPROWS*128; // 128 x 128

    const int row0 = blockIdx.x * OPROWS;
    const int tid = threadIdx.x;
    const int tr = tid >> 4, tc = tid & 15;

    float acc[4][8];
#pragma unroll
    for (int i = 0; i < 4; i++)
#pragma unroll
        for (int j = 0; j < 8; j++) acc[i][j] = 0.f;

    for (int kc = 0; kc < 4; kc++) {
        __syncthreads();
        for (int i = tid; i < OPROWS * 32; i += 256) {
            int r = i >> 5, c4 = (i & 31) * 4;
            *(float4*)(sA + r * 128 + c4) =
                *(const float4*)(g_obar + (size_t)(row0 + r) * 512 + kc * 128 + c4);
        }
        for (int i = tid; i < 128 * 32; i += 256) {
            int r = i >> 5, c4 = (i & 31) * 4;
            *(float4*)(sB + r * 128 + c4) =
                *(const float4*)(Wo + (size_t)(kc * 128 + r) * 128 + c4);
        }
        __syncthreads();
        for (int k = 0; k < 128; k++) {
            float b8[8];
#pragma unroll
            for (int j = 0; j < 8; j++) b8[j] = sB[k * 128 + tc + 16 * j];
#pragma unroll
            for (int i = 0; i < 4; i++) {
                float a = sA[(tr * 4 + i) * 128 + k];
#pragma unroll
                for (int j = 0; j < 8; j++) acc[i][j] = fmaf(a, b8[j], acc[i][j]);
            }
        }
    }
#pragma unroll
    for (int i = 0; i < 4; i++) {
        int row = row0 + tr * 4 + i;
#pragma unroll
        for (int j = 0; j < 8; j++) {
            int c = tc + 16 * j;
            out[(size_t)row * 128 + c] = acc[i][j] + bo[c];
        }
    }
}

// ----------------------------------------------------------------------------
// Launch
// ----------------------------------------------------------------------------
extern "C" void kernel_launch(void* const* d_in, const int* in_sizes, int n_in,
                              void* d_out, int out_size)
{
    const float* x   = (const float*)d_in[0];
    const float* pos = (const float*)d_in[1];
    const float* Wq  = (const float*)d_in[2];
    const float* Wo  = (const float*)d_in[3];
    const float* bo  = (const float*)d_in[4];
    float* out = (float*)d_out;

    int write_tail = (out_size >= OUT_ELEMS + TAIL) ? 1 : 0;

    const int group_smem = (9 * QSTRIDE + 648 + 72 + 18 + 16) * 4;
    const int op_smem = (OPROWS * 128 + 128 * 128) * 4;

    static int attr_set = 0;
    if (!attr_set) {
        cudaFuncSetAttribute(gemm_kernel, cudaFuncAttributeMaxDynamicSharedMemorySize, GEMM_SMEM);
        cudaFuncSetAttribute(group_kernel, cudaFuncAttributeMaxDynamicSharedMemorySize, group_smem);
        cudaFuncSetAttribute(outproj_kernel, cudaFuncAttributeMaxDynamicSharedMemorySize, op_smem);
        attr_set = 1;
    }

    wprep_kernel<<<(NTILES * 16384 + 255) / 256, 256>>>(Wq);
    fps_kernel<<<BB, 512>>>(pos);
    knn_kernel<<<(BB * MM) / 8, 256>>>(pos, out, write_tail);
    rope_kernel<<<(NROPE + 255) / 256, 256>>>();
    gemm_kernel<<<MTILES, 256, GEMM_SMEM>>>(x);
    group_kernel<<<BB * TT * MM, 256, group_smem>>>(Wq);
    outproj_kernel<<<BB * TT * MM / OPROWS, 256, op_smem>>>(Wo, bo, out);
}

// round 8
// speedup vs baseline: 1.6034x; 1.0122x over previous
#include <cuda_runtime.h>
#include <cuda_bf16.h>
#include <math.h>
#include <stdint.h>

// Problem constants (fixed shapes)
#define BB 2
#define TT 4
#define NN 8192
#define CC 128
#define MM 1024
#define KK 9
#define HH 8
#define DHH 64
#define QKVC 1536         // 3 * HH * DHH
#define OUT_ELEMS (BB*TT*MM*CC)   // 1048576
#define TAIL (BB*MM*2)            // 4096
#define QSTRIDE 1540
#define NROPE (BB*MM*KK*32)       // 589824
#define NROWS (BB*TT*NN)          // 65536 rows of P
#define NTILES 12                 // 1536/128
#define MTILES 512                // 65536/128
#define GEMM_CTAS 146             // blocks 2..147 of the fused kernel

// smem row stride for mma tiles: 136 bf16 = 272 bytes (conflict-free ldmatrix)
#define TSTRIDE 136
#define TILE_B  (128 * TSTRIDE * 2)   // 34816 bytes per 128x128 bf16 tile

// smem layout of fused kernel
#define SM_AHI 0
#define SM_ALO TILE_B
#define SM_B0  (2*TILE_B)             // B buf0: hi at +0, lo at +TILE_B
#define SM_B1  (4*TILE_B)             // B buf1
#define GEMM_SMEM (6*TILE_B)          // 208896 bytes

// ----------------------------------------------------------------------------
// Scratch (device globals; allocation-free)
// ----------------------------------------------------------------------------
__device__ int   g_pivot_idx[BB*MM];
__device__ int   g_nbr[BB*MM*KK];
__device__ float g_rel[BB*MM*KK*2];
__device__ float g_rsin[NROPE];
__device__ float g_rcos[NROPE];
__device__ float g_P[(size_t)NROWS * QKVC];                 // 402 MB scratch
__device__ float g_obar[BB*TT*MM * 512];                    // 16 MB
__device__ __align__(16) __nv_bfloat16 g_whi[NTILES*128*128];  // W1 bf16 hi, [ntile][n][k]
__device__ __align__(16) __nv_bfloat16 g_wlo[NTILES*128*128];  // W1 bf16 lo

// ----------------------------------------------------------------------------
// mma.sync / ldmatrix / cp.async helpers (valid on plain sm_100)
// ----------------------------------------------------------------------------
__device__ __forceinline__ uint32_t smem_u32(const void* p) {
    uint32_t a;
    asm("{ .reg .u64 t; cvta.to.shared.u64 t, %1; cvt.u32.u64 %0, t; }" : "=r"(a) : "l"(p));
    return a;
}
__device__ __forceinline__ void ldsm_x4(uint32_t* r, uint32_t addr) {
    asm volatile("ldmatrix.sync.aligned.m8n8.x4.shared.b16 {%0,%1,%2,%3}, [%4];"
                 : "=r"(r[0]), "=r"(r[1]), "=r"(r[2]), "=r"(r[3]) : "r"(addr));
}
__device__ __forceinline__ void mma16816(float* c, const uint32_t* a, const uint32_t* b) {
    asm volatile("mma.sync.aligned.m16n8k16.row.col.f32.bf16.bf16.f32 "
                 "{%0,%1,%2,%3}, {%4,%5,%6,%7}, {%8,%9}, {%0,%1,%2,%3};"
                 : "+f"(c[0]), "+f"(c[1]), "+f"(c[2]), "+f"(c[3])
                 : "r"(a[0]), "r"(a[1]), "r"(a[2]), "r"(a[3]), "r"(b[0]), "r"(b[1]));
}
__device__ __forceinline__ void cp16(uint32_t dst, const void* src) {
    asm volatile("cp.async.cg.shared.global [%0], [%1], 16;" :: "r"(dst), "l"(src));
}
#define CP_COMMIT() asm volatile("cp.async.commit_group;" ::: "memory")
#define CP_WAIT(n)  asm volatile("cp.async.wait_group %0;" :: "n"(n) : "memory")

// ----------------------------------------------------------------------------
// FPS body (512 threads, one block per batch) -- bit-exact vs reference
// ----------------------------------------------------------------------------
__device__ void fps_body(const float* __restrict__ pos, int bb, char* dynsmem)
{
    const int tid = threadIdx.x;
    const float2* pb = (const float2*)(pos + (size_t)bb * NN * 2);

    float px[16], py[16], dist[16];
#pragma unroll
    for (int j = 0; j < 16; j++) {
        float2 v = pb[j * 512 + tid];
        px[j] = v.x; py[j] = v.y; dist[j] = INFINITY;
    }

    unsigned long long* s_key = (unsigned long long*)dynsmem;  // [2][16]
    const int wid = tid >> 5, lane = tid & 31;

    float bx, by;
    { float2 p0 = pb[0]; bx = p0.x; by = p0.y; }
    if (tid == 0) g_pivot_idx[bb * MM] = 0;

    for (int s = 1; s < MM; s++) {
        unsigned bestd; int besti;
        {
            // numerically identical to reference: (dx*dx) + (dy*dy), no FMA
            float dx = __fsub_rn(px[0], bx), dy = __fsub_rn(py[0], by);
            float d  = __fadd_rn(__fmul_rn(dx, dx), __fmul_rn(dy, dy));
            dist[0]  = fminf(dist[0], d);
            bestd = __float_as_uint(dist[0]); besti = tid;
        }
#pragma unroll
        for (int j = 1; j < 16; j++) {
            float dx = __fsub_rn(px[j], bx), dy = __fsub_rn(py[j], by);
            float d  = __fadd_rn(__fmul_rn(dx, dx), __fmul_rn(dy, dy));
            dist[j]  = fminf(dist[j], d);
            unsigned db = __float_as_uint(dist[j]);
            if (db > bestd) { bestd = db; besti = j * 512 + tid; }
        }
        unsigned wmax = __reduce_max_sync(0xffffffffu, bestd);
        unsigned cand = (bestd == wmax) ? (unsigned)besti : 0x7fffffffu;
        unsigned wmin = __reduce_min_sync(0xffffffffu, cand);
        if (lane == 0)
            s_key[(s & 1) * 16 + wid] = ((unsigned long long)wmax << 32) | (unsigned)(~wmin);
        __syncthreads();
        unsigned long long best = s_key[(s & 1) * 16];
#pragma unroll
        for (int w = 1; w < 16; w++) {
            unsigned long long k2 = s_key[(s & 1) * 16 + w];
            if (k2 > best) best = k2;
        }
        int bi = (int)(~(unsigned)(best & 0xffffffffu));
        float2 bp = pb[bi];
        bx = bp.x; by = bp.y;
        if (tid == 0) g_pivot_idx[bb * MM + s] = bi;
    }
}

// ----------------------------------------------------------------------------
// Fused kernel: blocks 0,1 -> FPS; blocks 2..147 -> persistent GEMM
// GEMM: P = x @ W1 via mma.sync bf16 hi/lo (3 passes), cp.async dbuf B.
// 16 warps: wm = wid&3 (32-row slice), wn = wid>>2 (32-col slice)
// ----------------------------------------------------------------------------
__global__ void __launch_bounds__(512, 1) gemm_fps_kernel(const float* __restrict__ x,
                                                          const float* __restrict__ pos)
{
    extern __shared__ char smem[];
    if (blockIdx.x < 2) { fps_body(pos, blockIdx.x, smem); return; }

    const uint32_t sb = smem_u32(smem);
    const int tid  = threadIdx.x;
    const int wid  = tid >> 5, lane = tid & 31;
    const int wm   = wid & 3;        // m-slice (32 rows)
    const int wn   = wid >> 2;       // n-slice (32 cols)

    // ldmatrix per-lane base offsets
    const uint32_t a_off = (uint32_t)(((wm * 32 + (lane & 15)) * TSTRIDE + ((lane >> 4) << 3)) * 2);
    const uint32_t b_off = (uint32_t)(((wn * 32 + ((lane >> 4) << 3) + (lane & 7)) * TSTRIDE
                                      + (((lane >> 3) & 1) << 3)) * 2);

    for (int m = (int)blockIdx.x - 2; m < MTILES; m += GEMM_CTAS) {
        // prefetch B(0) into buf0 (overlaps A conversion)
        {
            const char* bh = (const char*)g_whi;
            const char* bl = (const char*)g_wlo;
            for (int i = tid; i < 2048; i += 512) {
                int row = i >> 4, ch = i & 15;
                uint32_t off = (uint32_t)((row * TSTRIDE + ch * 8) * 2);
                cp16(sb + SM_B0 + off, bh + i * 16);
                cp16(sb + SM_B0 + TILE_B + off, bl + i * 16);
            }
            CP_COMMIT();
        }

        // load + convert A tile (128x128 fp32 -> bf16 hi/lo)
        {
            const float4* xa = (const float4*)(x + (size_t)m * 128 * 128);
            for (int i = tid; i < 4096; i += 512) {
                int row = i >> 5, c = (i & 31) * 4;
                float4 v = xa[i];
                __nv_bfloat16 h0 = __float2bfloat16(v.x);
                __nv_bfloat16 h1 = __float2bfloat16(v.y);
                __nv_bfloat16 h2 = __float2bfloat16(v.z);
                __nv_bfloat16 h3 = __float2bfloat16(v.w);
                __nv_bfloat16 l0 = __float2bfloat16(v.x - __bfloat162float(h0));
                __nv_bfloat16 l1 = __float2bfloat16(v.y - __bfloat162float(h1));
                __nv_bfloat16 l2 = __float2bfloat16(v.z - __bfloat162float(h2));
                __nv_bfloat16 l3 = __float2bfloat16(v.w - __bfloat162float(h3));
                __nv_bfloat162* dh = (__nv_bfloat162*)(smem + SM_AHI + (row * TSTRIDE + c) * 2);
                __nv_bfloat162* dl = (__nv_bfloat162*)(smem + SM_ALO + (row * TSTRIDE + c) * 2);
                __nv_bfloat162 hp0; hp0.x = h0; hp0.y = h1;
                __nv_bfloat162 hp1; hp1.x = h2; hp1.y = h3;
                __nv_bfloat162 lp0; lp0.x = l0; lp0.y = l1;
                __nv_bfloat162 lp1; lp1.x = l2; lp1.y = l3;
                dh[0] = hp0; dh[1] = hp1;
                dl[0] = lp0; dl[1] = lp1;
            }
        }

        for (int nt = 0; nt < NTILES; nt++) {
            const uint32_t bufc = sb + ((nt & 1) ? SM_B1 : SM_B0);

            // prefetch B(nt+1) into the other buffer (its last readers synced at nt-1)
            if (nt + 1 < NTILES) {
                const char* bh = (const char*)(g_whi + (size_t)(nt + 1) * 16384);
                const char* bl = (const char*)(g_wlo + (size_t)(nt + 1) * 16384);
                uint32_t dst = sb + (((nt + 1) & 1) ? SM_B1 : SM_B0);
                for (int i = tid; i < 2048; i += 512) {
                    int row = i >> 4, ch = i & 15;
                    uint32_t off = (uint32_t)((row * TSTRIDE + ch * 8) * 2);
                    cp16(dst + off, bh + i * 16);
                    cp16(dst + TILE_B + off, bl + i * 16);
                }
                CP_COMMIT();
                CP_WAIT(1);          // B(nt) landed; B(nt+1) in flight
            } else {
                CP_WAIT(0);
            }
            __syncthreads();         // B(nt) + A visible to all warps

            float acc[32];
#pragma unroll
            for (int i = 0; i < 32; i++) acc[i] = 0.f;

            // 3 passes: (Ahi,Bhi), (Ahi,Blo), (Alo,Bhi)
#pragma unroll
            for (int pass = 0; pass < 3; pass++) {
                const uint32_t sa  = sb + (pass == 2 ? SM_ALO : SM_AHI) + a_off;
                const uint32_t sbb = bufc + (pass == 1 ? TILE_B : 0) + b_off;
#pragma unroll
                for (int ks = 0; ks < 8; ks++) {
                    uint32_t a0[4], a1[4];
                    ldsm_x4(a0, sa + ks * 32);
                    ldsm_x4(a1, sa + 16 * TSTRIDE * 2 + ks * 32);
#pragma unroll
                    for (int j2 = 0; j2 < 2; j2++) {
                        uint32_t b[4];
                        ldsm_x4(b, sbb + j2 * 16 * TSTRIDE * 2 + ks * 32);
                        mma16816(acc + (0 * 4 + j2 * 2 + 0) * 4, a0, b);
                        mma16816(acc + (0 * 4 + j2 * 2 + 1) * 4, a0, b + 2);
                        mma16816(acc + (1 * 4 + j2 * 2 + 0) * 4, a1, b);
                        mma16816(acc + (1 * 4 + j2 * 2 + 1) * 4, a1, b + 2);
                    }
                }
            }
            __syncthreads();         // all warps done reading buf(nt) (overwritten at nt+1)

            // epilogue: write fragment to g_P (register-only; overlaps next prefetch)
            {
                const int rbase = m * 128 + wm * 32 + (lane >> 2);
                const int cbase = nt * 128 + wn * 32 + (lane & 3) * 2;
#pragma unroll
                for (int i = 0; i < 2; i++) {
#pragma unroll
                    for (int j = 0; j < 4; j++) {
                        const float* c = acc + (i * 4 + j) * 4;
                        int r0 = rbase + i * 16;
                        int cc = cbase + j * 8;
                        *(float2*)(g_P + (size_t)r0 * QKVC + cc)       = make_float2(c[0], c[1]);
                        *(float2*)(g_P + (size_t)(r0 + 8) * QKVC + cc) = make_float2(c[2], c[3]);
                    }
                }
            }
        }
        __syncthreads();             // A region reused next m
    }
}

// ----------------------------------------------------------------------------
// Kernel 2: KNN (warp per pivot) + writes pivot_pos to output tail
// ----------------------------------------------------------------------------
__global__ void __launch_bounds__(256) knn_kernel(const float* __restrict__ pos,
                                                  float* __restrict__ outp,
                                                  int write_tail)
{
    const int gw   = blockIdx.x * (blockDim.x >> 5) + (threadIdx.x >> 5);
    const int lane = threadIdx.x & 31;
    const int bb   = gw >> 10;
    const float2* pb = (const float2*)(pos + (size_t)bb * NN * 2);
    const unsigned full = 0xffffffffu;

    const int pidx = g_pivot_idx[gw];
    const float2 pv = pb[pidx];
    const float a = __fadd_rn(__fmul_rn(pv.x, pv.x), __fmul_rn(pv.y, pv.y));

    float d[9]; int id[9];
#pragma unroll
    for (int q = 0; q < 9; q++) { d[q] = INFINITY; id[q] = 0x7fffffff; }

    for (int p = lane; p < NN; p += 32) {
        float2 q2 = pb[p];
        float b2  = __fadd_rn(__fmul_rn(q2.x, q2.x), __fmul_rn(q2.y, q2.y));
        float dot = __fadd_rn(__fmul_rn(pv.x, q2.x), __fmul_rn(pv.y, q2.y));
        float d2  = __fsub_rn(__fadd_rn(a, b2), __fmul_rn(2.0f, dot));
        if (d2 < d[8] || (d2 == d[8] && p < id[8])) {
            d[8] = d2; id[8] = p;
#pragma unroll
            for (int q = 8; q > 0; q--) {
                bool sw = (d[q] < d[q-1]) || (d[q] == d[q-1] && id[q] < id[q-1]);
                if (sw) {
                    float tv = d[q]; d[q] = d[q-1]; d[q-1] = tv;
                    int   ti = id[q]; id[q] = id[q-1]; id[q-1] = ti;
                }
            }
        }
    }
#pragma unroll
    for (int r = 0; r < 9; r++) {
        float bv = d[0]; int bi = id[0]; int bl = lane;
#pragma unroll
        for (int off = 16; off > 0; off >>= 1) {
            float ov = __shfl_down_sync(full, bv, off);
            int   oi = __shfl_down_sync(full, bi, off);
            int   ol = __shfl_down_sync(full, bl, off);
            if (ov < bv || (ov == bv && oi < bi)) { bv = ov; bi = oi; bl = ol; }
        }
        bi = __shfl_sync(full, bi, 0);
        bl = __shfl_sync(full, bl, 0);
        if (lane == bl) {
#pragma unroll
            for (int q = 0; q < 8; q++) { d[q] = d[q+1]; id[q] = id[q+1]; }
            d[8] = INFINITY; id[8] = 0x7fffffff;
        }
        if (lane == 0) {
            g_nbr[gw * KK + r] = bi;
            float2 q2 = pb[bi];
            g_rel[(gw * KK + r) * 2 + 0] = __fsub_rn(q2.x, pv.x);
            g_rel[(gw * KK + r) * 2 + 1] = __fsub_rn(q2.y, pv.y);
        }
    }
    if (lane == 0 && write_tail) {
        outp[OUT_ELEMS + gw * 2 + 0] = pv.x;
        outp[OUT_ELEMS + gw * 2 + 1] = pv.y;
    }
}

// ----------------------------------------------------------------------------
// sin/cos with explicit Cody-Waite range reduction (safe under fast-math)
// ----------------------------------------------------------------------------
__device__ __forceinline__ void sincos_red(float f, float* sn, float* cs)
{
    const float INV2PI = 0.15915494309189535f;
    const float C1 = 6.28318548202514648f;
    const float C2 = -1.74845560e-7f;
    float kq = rintf(f * INV2PI);
    float r = fmaf(-kq, C1, f);
    r = fmaf(-kq, C2, r);
    *sn = sinf(r);
    *cs = cosf(r);
}

// Kernel 2.5: precompute RoPE sin/cos (t-invariant)
__global__ void __launch_bounds__(256) rope_kernel()
{
    int idx = blockIdx.x * 256 + threadIdx.x;
    if (idx >= NROPE) return;
    int i    = idx & 15;
    int half = (idx >> 4) & 1;
    int rest = idx >> 5;
    int s    = rest % 9;
    int g    = rest / 9;
    float rel = g_rel[(g * KK + s) * 2 + half];
    float invf = __powf(10000.0f, -(float)i * (1.0f / 16.0f));
    float f = rel * 2048.0f * invf;
    float sn, cs;
    sincos_red(f, &sn, &cs);
    g_rsin[idx] = sn;
    g_rcos[idx] = cs;
}

// ----------------------------------------------------------------------------
// Kernel 0: convert W1 (=W_qkv rows 0..127) into bf16 hi/lo, layout [ntile][n][k]
// ----------------------------------------------------------------------------
__global__ void __launch_bounds__(256) wprep_kernel(const float* __restrict__ Wq)
{
    int idx = blockIdx.x * 256 + threadIdx.x;
    if (idx >= NTILES * 16384) return;
    int ntile = idx >> 14;
    int e = idx & 16383;
    int n = e >> 7, k = e & 127;
    float w = Wq[(size_t)k * QKVC + ntile * 128 + n];
    __nv_bfloat16 hi = __float2bfloat16(w);
    __nv_bfloat16 lo = __float2bfloat16(w - __bfloat162float(hi));
    g_whi[idx] = hi;
    g_wlo[idx] = lo;
}

// ----------------------------------------------------------------------------
// Kernel 4: gather P + rel update + RoPE + attention + mean -> g_obar
// ----------------------------------------------------------------------------
__global__ void __launch_bounds__(256) group_kernel(const float* __restrict__ Wq)
{
    extern __shared__ float sm[];
    float* s_qkv  = sm;                        // 9 * QSTRIDE
    float* s_dots = s_qkv + 9 * QSTRIDE;       // 648
    float* s_w    = s_dots + 648;              // 72
    float* s_rel  = s_w + 72;                  // 18
    int*   s_nbr  = (int*)(s_rel + 18);        // 9 (+pad)

    const int g   = blockIdx.x;
    const int bb  = g >> 12;
    const int tt  = (g >> 10) & 3;
    const int mi  = g & 1023;
    const int tid = threadIdx.x;
    const int base = (bb << 10) + mi;          // b*M + m

    if (tid < 9)  s_nbr[tid] = g_nbr[base * KK + tid];
    if (tid < 18) s_rel[tid] = g_rel[base * KK * 2 + tid];
    __syncthreads();

    // qkv[s] = P[nbr[s]] + rel_x * W2a + rel_y * W2b
    const float* Pbt = g_P + (size_t)((bb * TT + tt)) * NN * QKVC;
    const float* W2a = Wq + (size_t)128 * QKVC;
    const float* W2b = Wq + (size_t)129 * QKVC;
    for (int idx = tid; idx < 9 * 384; idx += 256) {
        int sl = idx / 384;
        int c4 = idx - sl * 384;
        float4 p  = *(const float4*)(Pbt + (size_t)s_nbr[sl] * QKVC + c4 * 4);
        float4 wa = *(const float4*)(W2a + c4 * 4);
        float4 wb = *(const float4*)(W2b + c4 * 4);
        float rx = s_rel[sl * 2], ry = s_rel[sl * 2 + 1];
        float4 r;
        r.x = p.x + rx * wa.x + ry * wb.x;
        r.y = p.y + rx * wa.y + ry * wb.y;
        r.z = p.z + rx * wa.z + ry * wb.z;
        r.w = p.w + rx * wa.w + ry * wb.w;
        *(float4*)(s_qkv + sl * QSTRIDE + c4 * 4) = r;
    }
    __syncthreads();

    // 2D RoPE on q,k using precomputed sin/cos. tid -> (head, half, i)
    {
        const int h = tid >> 5, half = (tid >> 4) & 1, i = tid & 15;
        const int bq = h * 64 + half * 32 + i;
#pragma unroll
        for (int s = 0; s < 9; s++) {
            int ridx = ((base * KK + s) * 2 + half) * 16 + i;
            float sn = g_rsin[ridx];
            float cs = g_rcos[ridx];
            float* row = s_qkv + s * QSTRIDE;
            float qa = row[bq], qb = row[bq + 16];
            row[bq]      = qa * cs - qb * sn;
            row[bq + 16] = qb * cs + qa * sn;
            float ka = row[512 + bq], kb = row[512 + bq + 16];
            row[512 + bq]      = ka * cs - kb * sn;
            row[512 + bq + 16] = kb * cs + ka * sn;
        }
    }
    __syncthreads();

    // dots[h][i][j] = scale * q_i . k_j
    for (int idx = tid; idx < 648; idx += 256) {
        int h = idx / 81, r = idx - h * 81;
        int qi = r / 9, kj = r - qi * 9;
        const float* qp = s_qkv + qi * QSTRIDE + h * 64;
        const float* kp = s_qkv + kj * QSTRIDE + 512 + h * 64;
        float a2 = 0.f;
#pragma unroll
        for (int dd = 0; dd < 64; dd++) a2 = fmaf(qp[dd], kp[dd], a2);
        s_dots[idx] = a2 * 0.125f;
    }
    __syncthreads();

    // softmax per (h,i) row
    if (tid < 72) {
        float* row = s_dots + tid * 9;
        float mx = row[0];
#pragma unroll
        for (int j = 1; j < 9; j++) mx = fmaxf(mx, row[j]);
        float sum = 0.f;
#pragma unroll
        for (int j = 0; j < 9; j++) { float e = expf(row[j] - mx); row[j] = e; sum += e; }
        float inv = 1.0f / sum;
#pragma unroll
        for (int j = 0; j < 9; j++) row[j] *= inv;
    }
    __syncthreads();

    // column sums of attn: w[h][j] = sum_i attn[h][i][j]
    if (tid < 72) {
        int h = tid / 9, j = tid - h * 9;
        float s2 = 0.f;
#pragma unroll
        for (int i = 0; i < 9; i++) s2 += s_dots[(h * 9 + i) * 9 + j];
        s_w[tid] = s2;
    }
    __syncthreads();

    // obar[c] = (1/9) * sum_j w[h][j] * v[j][d] -> global
    for (int c = tid; c < 512; c += 256) {
        int h = c >> 6, dd = c & 63;
        float a3 = 0.f;
#pragma unroll
        for (int j = 0; j < 9; j++)
            a3 = fmaf(s_w[h * 9 + j], s_qkv[j * QSTRIDE + 1024 + h * 64 + dd], a3);
        g_obar[(size_t)g * 512 + c] = a3 * (1.0f / 9.0f);
    }
}

// ----------------------------------------------------------------------------
// Kernel 5: out = obar @ W_out + b_out   (8192 x 128 x 512)
// ----------------------------------------------------------------------------
#define OPROWS 64
__global__ void __launch_bounds__(256) outproj_kernel(const float* __restrict__ Wo,
                                                      const float* __restrict__ bo,
                                                      float* __restrict__ out)
{
    extern __shared__ float smo[];
    float* sA = smo;             // 64 x 128
    float* sB = sA + OPROWS*128; // 128 x 128

    const int row0 = blockIdx.x * OPROWS;
    const int tid = threadIdx.x;
    const int tr = tid >> 4, tc = tid & 15;

    float acc[4][8];
#pragma unroll
    for (int i = 0; i < 4; i++)
#pragma unroll
        for (int j = 0; j < 8; j++) acc[i][j] = 0.f;

    for (int kc = 0; kc < 4; kc++) {
        __syncthreads();
        for (int i = tid; i < OPROWS * 32; i += 256) {
            int r = i >> 5, c4 = (i & 31) * 4;
            *(float4*)(sA + r * 128 + c4) =
                *(const float4*)(g_obar + (size_t)(row0 + r) * 512 + kc * 128 + c4);
        }
        for (int i = tid; i < 128 * 32; i += 256) {
            int r = i >> 5, c4 = (i & 31) * 4;
            *(float4*)(sB + r * 128 + c4) =
                *(const float4*)(Wo + (size_t)(kc * 128 + r) * 128 + c4);
        }
        __syncthreads();
        for (int k = 0; k < 128; k++) {
            float b8[8];
#pragma unroll
            for (int j = 0; j < 8; j++) b8[j] = sB[k * 128 + tc + 16 * j];
#pragma unroll
            for (int i = 0; i < 4; i++) {
                float a = sA[(tr * 4 + i) * 128 + k];
#pragma unroll
                for (int j = 0; j < 8; j++) acc[i][j] = fmaf(a, b8[j], acc[i][j]);
            }
        }
    }
#pragma unroll
    for (int i = 0; i < 4; i++) {
        int row = row0 + tr * 4 + i;
#pragma unroll
        for (int j = 0; j < 8; j++) {
            int c = tc + 16 * j;
            out[(size_t)row * 128 + c] = acc[i][j] + bo[c];
        }
    }
}

// ----------------------------------------------------------------------------
// Launch
// ----------------------------------------------------------------------------
extern "C" void kernel_launch(void* const* d_in, const int* in_sizes, int n_in,
                              void* d_out, int out_size)
{
    const float* x   = (const float*)d_in[0];
    const float* pos = (const float*)d_in[1];
    const float* Wq  = (const float*)d_in[2];
    const float* Wo  = (const float*)d_in[3];
    const float* bo  = (const float*)d_in[4];
    float* out = (float*)d_out;

    int write_tail = (out_size >= OUT_ELEMS + TAIL) ? 1 : 0;

    const int group_smem = (9 * QSTRIDE + 648 + 72 + 18 + 16) * 4;
    const int op_smem = (OPROWS * 128 + 128 * 128) * 4;

    static int attr_set = 0;
    if (!attr_set) {
        cudaFuncSetAttribute(gemm_fps_kernel, cudaFuncAttributeMaxDynamicSharedMemorySize, GEMM_SMEM);
        cudaFuncSetAttribute(group_kernel, cudaFuncAttributeMaxDynamicSharedMemorySize, group_smem);
        cudaFuncSetAttribute(outproj_kernel, cudaFuncAttributeMaxDynamicSharedMemorySize, op_smem);
        attr_set = 1;
    }

    wprep_kernel<<<(NTILES * 16384 + 255) / 256, 256>>>(Wq);
    gemm_fps_kernel<<<2 + GEMM_CTAS, 512, GEMM_SMEM>>>(x, pos);
    knn_kernel<<<(BB * MM) / 8, 256>>>(pos, out, write_tail);
    rope_kernel<<<(NROPE + 255) / 256, 256>>>();
    group_kernel<<<BB * TT * MM, 256, group_smem>>>(Wq);
    outproj_kernel<<<BB * TT * MM / OPROWS, 256, op_smem>>>(Wo, bo, out);
}